// round 1
// baseline (speedup 1.0000x reference)
#include <cuda_runtime.h>
#include <math.h>

#define BATCH   2
#define SEQLEN  4096
#define DMODEL  1024
#define DINNER  2048
#define NHEADS  32
#define HEADDIM 64
#define DSTATE  64
#define CONVDIM 2176            // DINNER + 2*DSTATE
#define DINPROJ 4256            // 2*DINNER + 2*DSTATE + NHEADS
#define BL      8192            // BATCH*SEQLEN

// ---------------- scratch (static device globals: no allocations) ----------
__device__ float g_u   [(size_t)BL * DMODEL];    //  32 MB  LN output
__device__ float g_zx  [(size_t)BL * DINPROJ];   // 139 MB  in_proj output
__device__ float g_xbca[(size_t)BL * CONVDIM];   //  71 MB  conv+silu output
__device__ float g_dt  [(size_t)BL * NHEADS];    //   1 MB  softplus(dt)
__device__ float g_y   [(size_t)BL * DINNER];    //  64 MB  scan output (+D*x)
__device__ float g_yn  [(size_t)BL * DINNER];    //  64 MB  gated+rmsnormed

// ---------------- packed f32x2 helpers (sm_103a) ---------------------------
#define PACK2(d, lo, hi) asm("mov.b64 %0, {%1, %2};" : "=l"(d) : "f"(lo), "f"(hi))
#define UNPK2(lo, hi, s) asm("mov.b64 {%0, %1}, %2;" : "=f"(lo), "=f"(hi) : "l"(s))
#define FMA2(c, a, b)    asm("fma.rn.f32x2 %0, %1, %2, %0;" : "+l"(c) : "l"(a), "l"(b))

// ---------------- block reduction helper -----------------------------------
__device__ __forceinline__ float block_sum256(float v, float* sh) {
    #pragma unroll
    for (int o = 16; o; o >>= 1) v += __shfl_xor_sync(0xffffffffu, v, o);
    int lane = threadIdx.x & 31, wid = threadIdx.x >> 5;
    __syncthreads();                 // protect sh against reuse across calls
    if (lane == 0) sh[wid] = v;
    __syncthreads();
    float t = 0.f;
    #pragma unroll
    for (int j = 0; j < 8; j++) t += sh[j];
    return t;
}

// ---------------- 1) LayerNorm ---------------------------------------------
__global__ void __launch_bounds__(256) ln_kernel(const float* __restrict__ x,
                                                 const float* __restrict__ w,
                                                 const float* __restrict__ bparm)
{
    __shared__ float sh[8];
    int row = blockIdx.x, tid = threadIdx.x;
    const float4* xr = (const float4*)(x + (size_t)row * DMODEL);
    float4 v = xr[tid];
    float s  = v.x + v.y + v.z + v.w;
    float mu = block_sum256(s, sh) * (1.f / DMODEL);
    float d0 = v.x - mu, d1 = v.y - mu, d2 = v.z - mu, d3 = v.w - mu;
    float vs = d0*d0 + d1*d1 + d2*d2 + d3*d3;
    float var = block_sum256(vs, sh) * (1.f / DMODEL);
    float inv = rsqrtf(var + 1e-5f);
    float4 wv = ((const float4*)w)[tid];
    float4 bv = ((const float4*)bparm)[tid];
    float4 o;
    o.x = d0 * inv * wv.x + bv.x;
    o.y = d1 * inv * wv.y + bv.y;
    o.z = d2 * inv * wv.z + bv.z;
    o.w = d3 * inv * wv.w + bv.w;
    ((float4*)(g_u + (size_t)row * DMODEL))[tid] = o;
}

// ---------------- 2/6) NT GEMM: C[M,N] = A[M,K] * W[N,K]^T -----------------
// M = BL fixed. 128x128x8 tile, double-buffered smem, 8x8 microtile in f32x2.
template<int N, int K, bool SECOND>
__global__ void __launch_bounds__(256) gemm_nt(const float* __restrict__ W,
                                               const float* __restrict__ resid,
                                               float* __restrict__ outp)
{
    const float* __restrict__ Aptr = SECOND ? g_yn : g_u;
    float* __restrict__ Cptr       = SECOND ? outp : g_zx;

    __shared__ float As[2][8][132];
    __shared__ float Bs[2][8][132];

    int tid = threadIdx.x;
    int bm = blockIdx.y, bn = blockIdx.x;

    // staging: thread loads one float4 of A and one of B per k-tile
    int rL = tid >> 1;               // 0..127 : tile row
    int kc = (tid & 1) * 4;          // k sub-offset 0 or 4
    const float* Ag = Aptr + (size_t)(bm * 128 + rL) * K + kc;
    int eB = bn * 128 + rL;
    const float* Bg = W + (size_t)eB * K + kc;
    bool bok = eB < N;

    float4 av = *(const float4*)Ag;
    float4 bv = bok ? *(const float4*)Bg : make_float4(0.f, 0.f, 0.f, 0.f);
    As[0][kc+0][rL] = av.x; As[0][kc+1][rL] = av.y;
    As[0][kc+2][rL] = av.z; As[0][kc+3][rL] = av.w;
    Bs[0][kc+0][rL] = bv.x; Bs[0][kc+1][rL] = bv.y;
    Bs[0][kc+2][rL] = bv.z; Bs[0][kc+3][rL] = bv.w;
    __syncthreads();

    int tx = tid & 15, ty = tid >> 4;
    int m0 = ty * 8, n0 = tx * 8;

    unsigned long long cc[8][4];
    #pragma unroll
    for (int i = 0; i < 8; i++)
        #pragma unroll
        for (int j = 0; j < 4; j++) cc[i][j] = 0ull;

    const int NKT = K / 8;
    #pragma unroll 1
    for (int kt = 0; kt < NKT; kt++) {
        int buf = kt & 1;
        float4 av2, bv2;
        bool more = (kt + 1 < NKT);
        if (more) {
            av2 = *(const float4*)(Ag + (size_t)(kt + 1) * 8);
            bv2 = bok ? *(const float4*)(Bg + (size_t)(kt + 1) * 8)
                      : make_float4(0.f, 0.f, 0.f, 0.f);
        }
        #pragma unroll
        for (int k = 0; k < 8; k++) {
            float4 a0 = *(const float4*)&As[buf][k][m0];
            float4 a1 = *(const float4*)&As[buf][k][m0 + 4];
            float4 b0 = *(const float4*)&Bs[buf][k][n0];
            float4 b1 = *(const float4*)&Bs[buf][k][n0 + 4];
            unsigned long long bb0, bb1, bb2, bb3;
            PACK2(bb0, b0.x, b0.y); PACK2(bb1, b0.z, b0.w);
            PACK2(bb2, b1.x, b1.y); PACK2(bb3, b1.z, b1.w);
            float am[8] = {a0.x, a0.y, a0.z, a0.w, a1.x, a1.y, a1.z, a1.w};
            #pragma unroll
            for (int i = 0; i < 8; i++) {
                unsigned long long aa; PACK2(aa, am[i], am[i]);
                FMA2(cc[i][0], aa, bb0);
                FMA2(cc[i][1], aa, bb1);
                FMA2(cc[i][2], aa, bb2);
                FMA2(cc[i][3], aa, bb3);
            }
        }
        if (more) {
            int nb = buf ^ 1;
            As[nb][kc+0][rL] = av2.x; As[nb][kc+1][rL] = av2.y;
            As[nb][kc+2][rL] = av2.z; As[nb][kc+3][rL] = av2.w;
            Bs[nb][kc+0][rL] = bv2.x; Bs[nb][kc+1][rL] = bv2.y;
            Bs[nb][kc+2][rL] = bv2.z; Bs[nb][kc+3][rL] = bv2.w;
        }
        __syncthreads();
    }

    #pragma unroll
    for (int i = 0; i < 8; i++) {
        int r  = bm * 128 + m0 + i;
        int c0 = bn * 128 + n0;
        float v[8];
        UNPK2(v[0], v[1], cc[i][0]); UNPK2(v[2], v[3], cc[i][1]);
        UNPK2(v[4], v[5], cc[i][2]); UNPK2(v[6], v[7], cc[i][3]);
        size_t base = (size_t)r * N + c0;
        if (SECOND) {
            #pragma unroll
            for (int j = 0; j < 8; j++) v[j] += resid[base + j];
        }
        if (c0 < N)
            *(float4*)(Cptr + base)     = make_float4(v[0], v[1], v[2], v[3]);
        if (c0 + 4 < N)
            *(float4*)(Cptr + base + 4) = make_float4(v[4], v[5], v[6], v[7]);
    }
}

// ---------------- 3) causal depthwise conv(4) + SiLU -----------------------
__global__ void __launch_bounds__(256) conv_silu_kernel(const float* __restrict__ conv_w,
                                                        const float* __restrict__ conv_b)
{
    int i = blockIdx.y;                       // row in [0, BL)
    int c = blockIdx.x * 256 + threadIdx.x;   // channel
    if (c >= CONVDIM) return;
    int b = i >> 12;                          // SEQLEN = 4096
    int l = i & 4095;
    float w0 = conv_w[c*4+0], w1 = conv_w[c*4+1];
    float w2 = conv_w[c*4+2], w3 = conv_w[c*4+3];
    const float* col = g_zx + (size_t)(b << 12) * DINPROJ + DINNER + c;
    float s = conv_b[c];
    if (l >= 3) s += col[(size_t)(l-3) * DINPROJ] * w0;
    if (l >= 2) s += col[(size_t)(l-2) * DINPROJ] * w1;
    if (l >= 1) s += col[(size_t)(l-1) * DINPROJ] * w2;
    s += col[(size_t)l * DINPROJ] * w3;
    s = s / (1.f + expf(-s));                 // SiLU
    g_xbca[(size_t)i * CONVDIM + c] = s;
}

// ---------------- 3b) softplus(dt + dt_bias) -------------------------------
__global__ void __launch_bounds__(256) dt_kernel(const float* __restrict__ dt_bias)
{
    int idx = blockIdx.x * 256 + threadIdx.x;     // < BL*NHEADS
    int i = idx >> 5, hh = idx & 31;
    float v = g_zx[(size_t)i * DINPROJ + (DINNER + CONVDIM) + hh] + dt_bias[hh];
    g_dt[idx] = (v > 20.f) ? v : log1pf(expf(v));
}

// ---------------- 4) sequential selective-state scan -----------------------
// grid = BATCH*NHEADS*2 = 128 blocks (p split in halves of 32), 256 threads.
// Thread (tid): p = half*32 + tid/8, owns n = (tid&7)*8 .. +8 states.
__global__ void __launch_bounds__(256) scan_kernel(const float* __restrict__ A_log,
                                                   const float* __restrict__ Dp)
{
    int bx   = blockIdx.x;
    int b    = bx >> 6;
    int h    = (bx >> 1) & 31;
    int half = bx & 1;
    int tid  = threadIdx.x;
    int pl   = tid >> 3;
    int p    = half * 32 + pl;
    int nb   = (tid & 7) * 8;

    float Ah = -expf(A_log[h]);
    float Dh = Dp[h];

    float hreg[8];
    #pragma unroll
    for (int j = 0; j < 8; j++) hreg[j] = 0.f;

    const float* base = g_xbca + (size_t)b * SEQLEN * CONVDIM;
    const float* dtb  = g_dt   + (size_t)b * SEQLEN * NHEADS + h;
    float*       yb   = g_y    + (size_t)b * SEQLEN * DINNER + h * HEADDIM + p;

    // software pipeline: prefetch step 0
    float  dt_c = dtb[0];
    float  xv_c = base[h * 64 + p];
    float4 B0c = *(const float4*)(base + 2048 + nb);
    float4 B1c = *(const float4*)(base + 2048 + nb + 4);
    float4 C0c = *(const float4*)(base + 2112 + nb);
    float4 C1c = *(const float4*)(base + 2112 + nb + 4);

    for (int t = 0; t < SEQLEN; t++) {
        int tn = (t + 1 < SEQLEN) ? (t + 1) : t;
        const float* rown = base + (size_t)tn * CONVDIM;
        float  dt_n = dtb[(size_t)tn * NHEADS];
        float  xv_n = rown[h * 64 + p];
        float4 B0n = *(const float4*)(rown + 2048 + nb);
        float4 B1n = *(const float4*)(rown + 2048 + nb + 4);
        float4 C0n = *(const float4*)(rown + 2112 + nb);
        float4 C1n = *(const float4*)(rown + 2112 + nb + 4);

        float dA  = expf(dt_c * Ah);
        float dtx = dt_c * xv_c;

        float acc0, acc1;
        hreg[0] = hreg[0] * dA + dtx * B0c.x;  acc0  = hreg[0] * C0c.x;
        hreg[1] = hreg[1] * dA + dtx * B0c.y;  acc1  = hreg[1] * C0c.y;
        hreg[2] = hreg[2] * dA + dtx * B0c.z;  acc0 += hreg[2] * C0c.z;
        hreg[3] = hreg[3] * dA + dtx * B0c.w;  acc1 += hreg[3] * C0c.w;
        hreg[4] = hreg[4] * dA + dtx * B1c.x;  acc0 += hreg[4] * C1c.x;
        hreg[5] = hreg[5] * dA + dtx * B1c.y;  acc1 += hreg[5] * C1c.y;
        hreg[6] = hreg[6] * dA + dtx * B1c.z;  acc0 += hreg[6] * C1c.z;
        hreg[7] = hreg[7] * dA + dtx * B1c.w;  acc1 += hreg[7] * C1c.w;
        float acc = acc0 + acc1;

        acc += __shfl_xor_sync(0xffffffffu, acc, 1, 8);
        acc += __shfl_xor_sync(0xffffffffu, acc, 2, 8);
        acc += __shfl_xor_sync(0xffffffffu, acc, 4, 8);
        if ((tid & 7) == 0)
            yb[(size_t)t * DINNER] = acc + Dh * xv_c;

        dt_c = dt_n; xv_c = xv_n;
        B0c = B0n; B1c = B1n; C0c = C0n; C1c = C1n;
    }
}

// ---------------- 5) gate (y * silu(z)) + RMSNorm --------------------------
__global__ void __launch_bounds__(256) gate_rms_kernel(const float* __restrict__ norm_w)
{
    __shared__ float sh[8];
    int row = blockIdx.x, tid = threadIdx.x;
    const float4* y4 = (const float4*)(g_y  + (size_t)row * DINNER);
    const float4* z4 = (const float4*)(g_zx + (size_t)row * DINPROJ);
    float4 a0 = y4[tid], a1 = y4[tid + 256];
    float4 z0 = z4[tid], z1 = z4[tid + 256];
    float g[8];
    g[0] = a0.x * (z0.x / (1.f + expf(-z0.x)));
    g[1] = a0.y * (z0.y / (1.f + expf(-z0.y)));
    g[2] = a0.z * (z0.z / (1.f + expf(-z0.z)));
    g[3] = a0.w * (z0.w / (1.f + expf(-z0.w)));
    g[4] = a1.x * (z1.x / (1.f + expf(-z1.x)));
    g[5] = a1.y * (z1.y / (1.f + expf(-z1.y)));
    g[6] = a1.z * (z1.z / (1.f + expf(-z1.z)));
    g[7] = a1.w * (z1.w / (1.f + expf(-z1.w)));
    float ss = 0.f;
    #pragma unroll
    for (int j = 0; j < 8; j++) ss += g[j] * g[j];
    float tot = block_sum256(ss, sh);
    float inv = rsqrtf(tot * (1.f / DINNER) + 1e-5f);
    float4 w0 = ((const float4*)norm_w)[tid];
    float4 w1 = ((const float4*)norm_w)[tid + 256];
    float4 o0, o1;
    o0.x = g[0] * inv * w0.x; o0.y = g[1] * inv * w0.y;
    o0.z = g[2] * inv * w0.z; o0.w = g[3] * inv * w0.w;
    o1.x = g[4] * inv * w1.x; o1.y = g[5] * inv * w1.y;
    o1.z = g[6] * inv * w1.z; o1.w = g[7] * inv * w1.w;
    float4* yn4 = (float4*)(g_yn + (size_t)row * DINNER);
    yn4[tid] = o0;
    yn4[tid + 256] = o1;
}

// ---------------- launcher -------------------------------------------------
extern "C" void kernel_launch(void* const* d_in, const int* in_sizes, int n_in,
                              void* d_out, int out_size)
{
    const float* x       = (const float*)d_in[0];
    const float* ln_w    = (const float*)d_in[1];
    const float* ln_b    = (const float*)d_in[2];
    const float* W_in    = (const float*)d_in[3];
    const float* conv_w  = (const float*)d_in[4];
    const float* conv_b  = (const float*)d_in[5];
    const float* dt_bias = (const float*)d_in[6];
    const float* A_log   = (const float*)d_in[7];
    const float* Dp      = (const float*)d_in[8];
    const float* norm_w  = (const float*)d_in[9];
    const float* W_out   = (const float*)d_in[10];
    float* out = (float*)d_out;

    ln_kernel<<<BL, 256>>>(x, ln_w, ln_b);

    gemm_nt<DINPROJ, DMODEL, false>
        <<<dim3((DINPROJ + 127) / 128, BL / 128), 256>>>(W_in, nullptr, nullptr);

    conv_silu_kernel<<<dim3((CONVDIM + 255) / 256, BL), 256>>>(conv_w, conv_b);
    dt_kernel<<<BL * NHEADS / 256, 256>>>(dt_bias);

    scan_kernel<<<BATCH * NHEADS * 2, 256>>>(A_log, Dp);

    gate_rms_kernel<<<BL, 256>>>(norm_w);

    gemm_nt<DMODEL, DINNER, true>
        <<<dim3(DMODEL / 128, BL / 128), 256>>>(W_out, x, out);
}

// round 3
// speedup vs baseline: 1.1550x; 1.1550x over previous
#include <cuda_runtime.h>
#include <cstdint>
#include <math.h>

#define BATCH   2
#define SEQLEN  4096
#define DMODEL  1024
#define DINNER  2048
#define NHEADS  32
#define HEADDIM 64
#define DSTATE  64
#define CONVDIM 2176            // DINNER + 2*DSTATE
#define DINPROJ 4256            // 2*DINNER + 2*DSTATE + NHEADS
#define BL      8192            // BATCH*SEQLEN

// ---------------- scratch (static device globals: no allocations) ----------
__device__ float g_u   [(size_t)BL * DMODEL];
__device__ float g_zx  [(size_t)BL * DINPROJ];
__device__ float g_xbca[(size_t)BL * CONVDIM];
__device__ float g_dt  [(size_t)BL * NHEADS];
__device__ float g_y   [(size_t)BL * DINNER];
__device__ float g_yn  [(size_t)BL * DINNER];

// ---------------- tf32 helpers ---------------------------------------------
__device__ __forceinline__ float tf32_rna(float a) {
    uint32_t u;
    asm("cvt.rna.tf32.f32 %0, %1;" : "=r"(u) : "f"(a));
    return __uint_as_float(u);
}

#define MMA_TF32(d, a, b0, b1) \
    asm volatile("mma.sync.aligned.m16n8k8.row.col.f32.tf32.tf32.f32 " \
        "{%0,%1,%2,%3}, {%4,%5,%6,%7}, {%8,%9}, {%0,%1,%2,%3};" \
        : "+f"((d)[0]), "+f"((d)[1]), "+f"((d)[2]), "+f"((d)[3]) \
        : "r"((a)[0]), "r"((a)[1]), "r"((a)[2]), "r"((a)[3]), \
          "r"(b0), "r"(b1))

// ======================= TF32x3 NT GEMM (mma.sync) =========================
// C[M,N] = A[M,K] * W[N,K]^T, fp32 in/out, 3xTF32 compensated.
// CTA tile 128x128, K-tile 32, double-buffered smem [row][36] (pad => LDS
// fragment loads conflict-free). 8 warps in 4x2, warp tile 32x64.
#define KT        32
#define LDP       36                       // padded row stride (floats)
#define OFF_ALO   (128 * LDP)              // 4608
#define OFF_BHI   (2 * 128 * LDP)          // 9216
#define OFF_BLO   (3 * 128 * LDP)          // 13824
#define STAGE_F   (4 * 128 * LDP)          // 18432 floats
#define SMEM_DYN  (2 * STAGE_F * 4)        // 147456 bytes

template<int N, int K, bool SECOND>
__global__ void __launch_bounds__(256, 1) gemm_tc(const float* __restrict__ Wm,
                                                  const float* __restrict__ resid,
                                                  float* __restrict__ outp)
{
    extern __shared__ float smf[];
    const float* __restrict__ Aptr = SECOND ? g_yn : g_u;
    float* __restrict__ Cptr       = SECOND ? outp : g_zx;

    int tid = threadIdx.x;
    int wid = tid >> 5, lane = tid & 31;
    int bm = blockIdx.y, bn = blockIdx.x;

    // ---- staging geometry: 4 float4 of A + 4 of B per K-tile per thread ----
    int r0 = tid >> 3;                    // 0..31
    int c4 = (tid & 7) * 4;               // 0..28
    const float* Ag = Aptr + (size_t)(bm * 128 + r0) * K + c4;
    int nr0 = bn * 128 + r0;
    const float* Bg = Wm + (size_t)nr0 * K + c4;

    float4 a[4], b[4];
    auto ldg = [&](int kt) {
        #pragma unroll
        for (int i = 0; i < 4; i++)
            a[i] = *(const float4*)(Ag + (size_t)(32 * i) * K + kt * KT);
        #pragma unroll
        for (int i = 0; i < 4; i++) {
            int n = nr0 + 32 * i;
            b[i] = (n < N) ? *(const float4*)(Bg + (size_t)(32 * i) * K + kt * KT)
                           : make_float4(0.f, 0.f, 0.f, 0.f);
        }
    };
    auto sts = [&](int buf) {
        float* S = smf + buf * STAGE_F;
        #pragma unroll
        for (int i = 0; i < 4; i++) {
            int idx = (r0 + 32 * i) * LDP + c4;
            float4 h, l;
            h.x = tf32_rna(a[i].x); l.x = tf32_rna(a[i].x - h.x);
            h.y = tf32_rna(a[i].y); l.y = tf32_rna(a[i].y - h.y);
            h.z = tf32_rna(a[i].z); l.z = tf32_rna(a[i].z - h.z);
            h.w = tf32_rna(a[i].w); l.w = tf32_rna(a[i].w - h.w);
            *(float4*)(S + idx)           = h;
            *(float4*)(S + OFF_ALO + idx) = l;
            h.x = tf32_rna(b[i].x); l.x = tf32_rna(b[i].x - h.x);
            h.y = tf32_rna(b[i].y); l.y = tf32_rna(b[i].y - h.y);
            h.z = tf32_rna(b[i].z); l.z = tf32_rna(b[i].z - h.z);
            h.w = tf32_rna(b[i].w); l.w = tf32_rna(b[i].w - h.w);
            *(float4*)(S + OFF_BHI + idx) = h;
            *(float4*)(S + OFF_BLO + idx) = l;
        }
    };

    // ---- compute geometry ----
    int wm = wid >> 1, wn = wid & 1;      // warp grid 4x2
    int g = lane >> 2, t = lane & 3;
    int aBase = (wm * 32 + g) * LDP + t;
    int bBase = (wn * 64 + g) * LDP + t;

    float d[2][8][4];
    #pragma unroll
    for (int mt = 0; mt < 2; mt++)
        #pragma unroll
        for (int nt = 0; nt < 8; nt++)
            #pragma unroll
            for (int j = 0; j < 4; j++) d[mt][nt][j] = 0.f;

    ldg(0); sts(0);
    __syncthreads();

    const int NKT = K / KT;
    #pragma unroll 1
    for (int kt = 0; kt < NKT; ++kt) {
        if (kt + 1 < NKT) ldg(kt + 1);

        const float* S = smf + (kt & 1) * STAGE_F;
        #pragma unroll
        for (int ks = 0; ks < 4; ks++) {
            int k0 = ks * 8;
            uint32_t ah[2][4], al[2][4];
            #pragma unroll
            for (int mt = 0; mt < 2; mt++) {
                int ab = aBase + mt * (16 * LDP) + k0;
                ah[mt][0] = __float_as_uint(S[ab]);
                ah[mt][1] = __float_as_uint(S[ab + 8 * LDP]);
                ah[mt][2] = __float_as_uint(S[ab + 4]);
                ah[mt][3] = __float_as_uint(S[ab + 8 * LDP + 4]);
                al[mt][0] = __float_as_uint(S[OFF_ALO + ab]);
                al[mt][1] = __float_as_uint(S[OFF_ALO + ab + 8 * LDP]);
                al[mt][2] = __float_as_uint(S[OFF_ALO + ab + 4]);
                al[mt][3] = __float_as_uint(S[OFF_ALO + ab + 8 * LDP + 4]);
            }
            #pragma unroll
            for (int nt = 0; nt < 8; nt++) {
                int bb = bBase + nt * (8 * LDP) + k0;
                uint32_t bh0 = __float_as_uint(S[OFF_BHI + bb]);
                uint32_t bh1 = __float_as_uint(S[OFF_BHI + bb + 4]);
                uint32_t bl0 = __float_as_uint(S[OFF_BLO + bb]);
                uint32_t bl1 = __float_as_uint(S[OFF_BLO + bb + 4]);
                #pragma unroll
                for (int mt = 0; mt < 2; mt++) {
                    MMA_TF32(d[mt][nt], ah[mt], bh0, bh1);
                    MMA_TF32(d[mt][nt], ah[mt], bl0, bl1);
                    MMA_TF32(d[mt][nt], al[mt], bh0, bh1);
                }
            }
        }
        __syncthreads();
        if (kt + 1 < NKT) {
            sts((kt + 1) & 1);
            __syncthreads();
        }
    }

    // ---- epilogue: direct fragment stores (float2), fused residual --------
    #pragma unroll
    for (int mt = 0; mt < 2; mt++) {
        int row = bm * 128 + wm * 32 + mt * 16 + g;
        #pragma unroll
        for (int nt = 0; nt < 8; nt++) {
            int col = bn * 128 + wn * 64 + nt * 8 + t * 2;
            if (col < N) {
                size_t i0 = (size_t)row * N + col;
                size_t i1 = (size_t)(row + 8) * N + col;
                float2 v0 = make_float2(d[mt][nt][0], d[mt][nt][1]);
                float2 v1 = make_float2(d[mt][nt][2], d[mt][nt][3]);
                if (SECOND) {
                    float2 r0v = *(const float2*)(resid + i0);
                    float2 r1v = *(const float2*)(resid + i1);
                    v0.x += r0v.x; v0.y += r0v.y;
                    v1.x += r1v.x; v1.y += r1v.y;
                }
                *(float2*)(Cptr + i0) = v0;
                *(float2*)(Cptr + i1) = v1;
            }
        }
    }
}

// ---------------- block reduction helper -----------------------------------
__device__ __forceinline__ float block_sum256(float v, float* sh) {
    #pragma unroll
    for (int o = 16; o; o >>= 1) v += __shfl_xor_sync(0xffffffffu, v, o);
    int lane = threadIdx.x & 31, wid = threadIdx.x >> 5;
    __syncthreads();
    if (lane == 0) sh[wid] = v;
    __syncthreads();
    float tt = 0.f;
    #pragma unroll
    for (int j = 0; j < 8; j++) tt += sh[j];
    return tt;
}

// ---------------- 1) LayerNorm ---------------------------------------------
__global__ void __launch_bounds__(256) ln_kernel(const float* __restrict__ x,
                                                 const float* __restrict__ w,
                                                 const float* __restrict__ bparm)
{
    __shared__ float sh[8];
    int row = blockIdx.x, tid = threadIdx.x;
    const float4* xr = (const float4*)(x + (size_t)row * DMODEL);
    float4 v = xr[tid];
    float s  = v.x + v.y + v.z + v.w;
    float mu = block_sum256(s, sh) * (1.f / DMODEL);
    float d0 = v.x - mu, d1 = v.y - mu, d2 = v.z - mu, d3 = v.w - mu;
    float vs = d0*d0 + d1*d1 + d2*d2 + d3*d3;
    float var = block_sum256(vs, sh) * (1.f / DMODEL);
    float inv = rsqrtf(var + 1e-5f);
    float4 wv = ((const float4*)w)[tid];
    float4 bv = ((const float4*)bparm)[tid];
    float4 o;
    o.x = d0 * inv * wv.x + bv.x;
    o.y = d1 * inv * wv.y + bv.y;
    o.z = d2 * inv * wv.z + bv.z;
    o.w = d3 * inv * wv.w + bv.w;
    ((float4*)(g_u + (size_t)row * DMODEL))[tid] = o;
}

// ---------------- 3) causal depthwise conv(4) + SiLU -----------------------
__global__ void __launch_bounds__(256) conv_silu_kernel(const float* __restrict__ conv_w,
                                                        const float* __restrict__ conv_b)
{
    int i = blockIdx.y;
    int c = blockIdx.x * 256 + threadIdx.x;
    if (c >= CONVDIM) return;
    int b = i >> 12;
    int l = i & 4095;
    float w0 = conv_w[c*4+0], w1 = conv_w[c*4+1];
    float w2 = conv_w[c*4+2], w3 = conv_w[c*4+3];
    const float* col = g_zx + (size_t)(b << 12) * DINPROJ + DINNER + c;
    float s = conv_b[c];
    if (l >= 3) s += col[(size_t)(l-3) * DINPROJ] * w0;
    if (l >= 2) s += col[(size_t)(l-2) * DINPROJ] * w1;
    if (l >= 1) s += col[(size_t)(l-1) * DINPROJ] * w2;
    s += col[(size_t)l * DINPROJ] * w3;
    s = s / (1.f + expf(-s));
    g_xbca[(size_t)i * CONVDIM + c] = s;
}

// ---------------- 3b) softplus(dt + dt_bias) -------------------------------
__global__ void __launch_bounds__(256) dt_kernel(const float* __restrict__ dt_bias)
{
    int idx = blockIdx.x * 256 + threadIdx.x;
    int i = idx >> 5, hh = idx & 31;
    float v = g_zx[(size_t)i * DINPROJ + (DINNER + CONVDIM) + hh] + dt_bias[hh];
    g_dt[idx] = (v > 20.f) ? v : log1pf(expf(v));
}

// ---------------- 4) sequential selective-state scan -----------------------
__global__ void __launch_bounds__(256) scan_kernel(const float* __restrict__ A_log,
                                                   const float* __restrict__ Dp)
{
    int bx   = blockIdx.x;
    int b    = bx >> 6;
    int h    = (bx >> 1) & 31;
    int half = bx & 1;
    int tid  = threadIdx.x;
    int pl   = tid >> 3;
    int p    = half * 32 + pl;
    int nb   = (tid & 7) * 8;

    float Ah = -expf(A_log[h]);
    float Dh = Dp[h];

    float hreg[8];
    #pragma unroll
    for (int j = 0; j < 8; j++) hreg[j] = 0.f;

    const float* base = g_xbca + (size_t)b * SEQLEN * CONVDIM;
    const float* dtb  = g_dt   + (size_t)b * SEQLEN * NHEADS + h;
    float*       yb   = g_y    + (size_t)b * SEQLEN * DINNER + h * HEADDIM + p;

    float  dt_c = dtb[0];
    float  xv_c = base[h * 64 + p];
    float4 B0c = *(const float4*)(base + 2048 + nb);
    float4 B1c = *(const float4*)(base + 2048 + nb + 4);
    float4 C0c = *(const float4*)(base + 2112 + nb);
    float4 C1c = *(const float4*)(base + 2112 + nb + 4);

    for (int tstep = 0; tstep < SEQLEN; tstep++) {
        int tn = (tstep + 1 < SEQLEN) ? (tstep + 1) : tstep;
        const float* rown = base + (size_t)tn * CONVDIM;
        float  dt_n = dtb[(size_t)tn * NHEADS];
        float  xv_n = rown[h * 64 + p];
        float4 B0n = *(const float4*)(rown + 2048 + nb);
        float4 B1n = *(const float4*)(rown + 2048 + nb + 4);
        float4 C0n = *(const float4*)(rown + 2112 + nb);
        float4 C1n = *(const float4*)(rown + 2112 + nb + 4);

        float dA  = expf(dt_c * Ah);
        float dtx = dt_c * xv_c;

        float acc0, acc1;
        hreg[0] = hreg[0] * dA + dtx * B0c.x;  acc0  = hreg[0] * C0c.x;
        hreg[1] = hreg[1] * dA + dtx * B0c.y;  acc1  = hreg[1] * C0c.y;
        hreg[2] = hreg[2] * dA + dtx * B0c.z;  acc0 += hreg[2] * C0c.z;
        hreg[3] = hreg[3] * dA + dtx * B0c.w;  acc1 += hreg[3] * C0c.w;
        hreg[4] = hreg[4] * dA + dtx * B1c.x;  acc0 += hreg[4] * C1c.x;
        hreg[5] = hreg[5] * dA + dtx * B1c.y;  acc1 += hreg[5] * C1c.y;
        hreg[6] = hreg[6] * dA + dtx * B1c.z;  acc0 += hreg[6] * C1c.z;
        hreg[7] = hreg[7] * dA + dtx * B1c.w;  acc1 += hreg[7] * C1c.w;
        float acc = acc0 + acc1;

        acc += __shfl_xor_sync(0xffffffffu, acc, 1, 8);
        acc += __shfl_xor_sync(0xffffffffu, acc, 2, 8);
        acc += __shfl_xor_sync(0xffffffffu, acc, 4, 8);
        if ((tid & 7) == 0)
            yb[(size_t)tstep * DINNER] = acc + Dh * xv_c;

        dt_c = dt_n; xv_c = xv_n;
        B0c = B0n; B1c = B1n; C0c = C0n; C1c = C1n;
    }
}

// ---------------- 5) gate (y * silu(z)) + RMSNorm --------------------------
__global__ void __launch_bounds__(256) gate_rms_kernel(const float* __restrict__ norm_w)
{
    __shared__ float sh[8];
    int row = blockIdx.x, tid = threadIdx.x;
    const float4* y4 = (const float4*)(g_y  + (size_t)row * DINNER);
    const float4* z4 = (const float4*)(g_zx + (size_t)row * DINPROJ);
    float4 a0 = y4[tid], a1 = y4[tid + 256];
    float4 z0 = z4[tid], z1 = z4[tid + 256];
    float g[8];
    g[0] = a0.x * (z0.x / (1.f + expf(-z0.x)));
    g[1] = a0.y * (z0.y / (1.f + expf(-z0.y)));
    g[2] = a0.z * (z0.z / (1.f + expf(-z0.z)));
    g[3] = a0.w * (z0.w / (1.f + expf(-z0.w)));
    g[4] = a1.x * (z1.x / (1.f + expf(-z1.x)));
    g[5] = a1.y * (z1.y / (1.f + expf(-z1.y)));
    g[6] = a1.z * (z1.z / (1.f + expf(-z1.z)));
    g[7] = a1.w * (z1.w / (1.f + expf(-z1.w)));
    float ss = 0.f;
    #pragma unroll
    for (int j = 0; j < 8; j++) ss += g[j] * g[j];
    float tot = block_sum256(ss, sh);
    float inv = rsqrtf(tot * (1.f / DINNER) + 1e-5f);
    float4 w0 = ((const float4*)norm_w)[tid];
    float4 w1 = ((const float4*)norm_w)[tid + 256];
    float4 o0, o1;
    o0.x = g[0] * inv * w0.x; o0.y = g[1] * inv * w0.y;
    o0.z = g[2] * inv * w0.z; o0.w = g[3] * inv * w0.w;
    o1.x = g[4] * inv * w1.x; o1.y = g[5] * inv * w1.y;
    o1.z = g[6] * inv * w1.z; o1.w = g[7] * inv * w1.w;
    float4* yn4 = (float4*)(g_yn + (size_t)row * DINNER);
    yn4[tid] = o0;
    yn4[tid + 256] = o1;
}

// ---------------- launcher -------------------------------------------------
extern "C" void kernel_launch(void* const* d_in, const int* in_sizes, int n_in,
                              void* d_out, int out_size)
{
    const float* x       = (const float*)d_in[0];
    const float* ln_w    = (const float*)d_in[1];
    const float* ln_b    = (const float*)d_in[2];
    const float* W_in    = (const float*)d_in[3];
    const float* conv_w  = (const float*)d_in[4];
    const float* conv_b  = (const float*)d_in[5];
    const float* dt_bias = (const float*)d_in[6];
    const float* A_log   = (const float*)d_in[7];
    const float* Dp      = (const float*)d_in[8];
    const float* norm_w  = (const float*)d_in[9];
    const float* W_out   = (const float*)d_in[10];
    float* out = (float*)d_out;

    cudaFuncSetAttribute(gemm_tc<DINPROJ, DMODEL, false>,
                         cudaFuncAttributeMaxDynamicSharedMemorySize, SMEM_DYN);
    cudaFuncSetAttribute(gemm_tc<DMODEL, DINNER, true>,
                         cudaFuncAttributeMaxDynamicSharedMemorySize, SMEM_DYN);

    ln_kernel<<<BL, 256>>>(x, ln_w, ln_b);

    gemm_tc<DINPROJ, DMODEL, false>
        <<<dim3((DINPROJ + 127) / 128, BL / 128), 256, SMEM_DYN>>>(W_in, nullptr, nullptr);

    conv_silu_kernel<<<dim3((CONVDIM + 255) / 256, BL), 256>>>(conv_w, conv_b);
    dt_kernel<<<BL * NHEADS / 256, 256>>>(dt_bias);

    scan_kernel<<<BATCH * NHEADS * 2, 256>>>(A_log, Dp);

    gate_rms_kernel<<<BL, 256>>>(norm_w);

    gemm_tc<DMODEL, DINNER, true>
        <<<dim3(DMODEL / 128, BL / 128), 256, SMEM_DYN>>>(W_out, x, out);
}

// round 4
// speedup vs baseline: 1.5911x; 1.3776x over previous
#include <cuda_runtime.h>
#include <cstdint>
#include <math.h>

#define BATCH   2
#define SEQLEN  4096
#define DMODEL  1024
#define DINNER  2048
#define NHEADS  32
#define HEADDIM 64
#define DSTATE  64
#define CONVDIM 2176            // DINNER + 2*DSTATE
#define DINPROJ 4256            // 2*DINNER + 2*DSTATE + NHEADS
#define BL      8192            // BATCH*SEQLEN

// ---------------- scratch (static device globals: no allocations) ----------
__device__ float g_u   [(size_t)BL * DMODEL];
__device__ float g_zx  [(size_t)BL * DINPROJ];
__device__ float g_xbca[(size_t)BL * CONVDIM];
__device__ float g_dt  [(size_t)BL * NHEADS];
__device__ float g_y   [(size_t)BL * DINNER];
__device__ float g_yn  [(size_t)BL * DINNER];

// ---------------- helpers ---------------------------------------------------
__device__ __forceinline__ uint32_t smem_u32(const void* p) {
    uint32_t a;
    asm("{ .reg .u64 t; cvta.to.shared.u64 t, %1; cvt.u32.u64 %0, t; }"
        : "=r"(a) : "l"(p));
    return a;
}
__device__ __forceinline__ float tf32_rna(float a) {
    uint32_t u;
    asm("cvt.rna.tf32.f32 %0, %1;" : "=r"(u) : "f"(a));
    return __uint_as_float(u);
}

#define MMA_TF32(d, a, b0, b1) \
    asm volatile("mma.sync.aligned.m16n8k8.row.col.f32.tf32.tf32.f32 " \
        "{%0,%1,%2,%3}, {%4,%5,%6,%7}, {%8,%9}, {%0,%1,%2,%3};" \
        : "+f"((d)[0]), "+f"((d)[1]), "+f"((d)[2]), "+f"((d)[3]) \
        : "r"((a)[0]), "r"((a)[1]), "r"((a)[2]), "r"((a)[3]), \
          "r"(b0), "r"(b1))

#define CP_ASYNC16(dst, src) \
    asm volatile("cp.async.ca.shared.global [%0], [%1], 16;" \
        :: "r"(dst), "l"(src) : "memory")
#define CP_ASYNC4(dst, src) \
    asm volatile("cp.async.ca.shared.global [%0], [%1], 4;" \
        :: "r"(dst), "l"(src) : "memory")
#define CP_COMMIT() asm volatile("cp.async.commit_group;" ::: "memory")
#define CP_WAIT6()  asm volatile("cp.async.wait_group 6;" ::: "memory")

// ======================= TF32x3 NT GEMM (mma.sync) =========================
// C[M,N] = A[M,K] * W[N,K]^T, fp32 in/out, 3xTF32 compensated.
// CTA tile 128x128, K-tile 32, double-buffered smem [row][36] (pad => LDS
// fragment loads conflict-free). 8 warps in 4x2, warp tile 32x64.
#define KT        32
#define LDP       36                       // padded row stride (floats)
#define OFF_ALO   (128 * LDP)              // 4608
#define OFF_BHI   (2 * 128 * LDP)          // 9216
#define OFF_BLO   (3 * 128 * LDP)          // 13824
#define STAGE_F   (4 * 128 * LDP)          // 18432 floats
#define SMEM_DYN  (2 * STAGE_F * 4)        // 147456 bytes

template<int N, int K, bool SECOND>
__global__ void __launch_bounds__(256, 1) gemm_tc(const float* __restrict__ Wm,
                                                  const float* __restrict__ resid,
                                                  float* __restrict__ outp)
{
    extern __shared__ float smf[];
    const float* __restrict__ Aptr = SECOND ? g_yn : g_u;
    float* __restrict__ Cptr       = SECOND ? outp : g_zx;

    int tid = threadIdx.x;
    int wid = tid >> 5, lane = tid & 31;
    int bm = blockIdx.y, bn = blockIdx.x;

    // ---- staging geometry: 4 float4 of A + 4 of B per K-tile per thread ----
    int r0 = tid >> 3;                    // 0..31
    int c4 = (tid & 7) * 4;               // 0..28
    const float* Ag = Aptr + (size_t)(bm * 128 + r0) * K + c4;
    int nr0 = bn * 128 + r0;
    const float* Bg = Wm + (size_t)nr0 * K + c4;

    float4 a[4], b[4];
    auto ldg = [&](int kt) {
        #pragma unroll
        for (int i = 0; i < 4; i++)
            a[i] = *(const float4*)(Ag + (size_t)(32 * i) * K + kt * KT);
        #pragma unroll
        for (int i = 0; i < 4; i++) {
            int n = nr0 + 32 * i;
            b[i] = (n < N) ? *(const float4*)(Bg + (size_t)(32 * i) * K + kt * KT)
                           : make_float4(0.f, 0.f, 0.f, 0.f);
        }
    };
    auto sts = [&](int buf) {
        float* S = smf + buf * STAGE_F;
        #pragma unroll
        for (int i = 0; i < 4; i++) {
            int idx = (r0 + 32 * i) * LDP + c4;
            float4 h, l;
            h.x = tf32_rna(a[i].x); l.x = tf32_rna(a[i].x - h.x);
            h.y = tf32_rna(a[i].y); l.y = tf32_rna(a[i].y - h.y);
            h.z = tf32_rna(a[i].z); l.z = tf32_rna(a[i].z - h.z);
            h.w = tf32_rna(a[i].w); l.w = tf32_rna(a[i].w - h.w);
            *(float4*)(S + idx)           = h;
            *(float4*)(S + OFF_ALO + idx) = l;
            h.x = tf32_rna(b[i].x); l.x = tf32_rna(b[i].x - h.x);
            h.y = tf32_rna(b[i].y); l.y = tf32_rna(b[i].y - h.y);
            h.z = tf32_rna(b[i].z); l.z = tf32_rna(b[i].z - h.z);
            h.w = tf32_rna(b[i].w); l.w = tf32_rna(b[i].w - h.w);
            *(float4*)(S + OFF_BHI + idx) = h;
            *(float4*)(S + OFF_BLO + idx) = l;
        }
    };

    // ---- compute geometry ----
    int wm = wid >> 1, wn = wid & 1;      // warp grid 4x2
    int g = lane >> 2, t = lane & 3;
    int aBase = (wm * 32 + g) * LDP + t;
    int bBase = (wn * 64 + g) * LDP + t;

    float d[2][8][4];
    #pragma unroll
    for (int mt = 0; mt < 2; mt++)
        #pragma unroll
        for (int nt = 0; nt < 8; nt++)
            #pragma unroll
            for (int j = 0; j < 4; j++) d[mt][nt][j] = 0.f;

    ldg(0); sts(0);
    __syncthreads();

    const int NKT = K / KT;
    #pragma unroll 1
    for (int kt = 0; kt < NKT; ++kt) {
        if (kt + 1 < NKT) ldg(kt + 1);

        const float* S = smf + (kt & 1) * STAGE_F;
        #pragma unroll
        for (int ks = 0; ks < 4; ks++) {
            int k0 = ks * 8;
            uint32_t ah[2][4], al[2][4];
            #pragma unroll
            for (int mt = 0; mt < 2; mt++) {
                int ab = aBase + mt * (16 * LDP) + k0;
                ah[mt][0] = __float_as_uint(S[ab]);
                ah[mt][1] = __float_as_uint(S[ab + 8 * LDP]);
                ah[mt][2] = __float_as_uint(S[ab + 4]);
                ah[mt][3] = __float_as_uint(S[ab + 8 * LDP + 4]);
                al[mt][0] = __float_as_uint(S[OFF_ALO + ab]);
                al[mt][1] = __float_as_uint(S[OFF_ALO + ab + 8 * LDP]);
                al[mt][2] = __float_as_uint(S[OFF_ALO + ab + 4]);
                al[mt][3] = __float_as_uint(S[OFF_ALO + ab + 8 * LDP + 4]);
            }
            #pragma unroll
            for (int nt = 0; nt < 8; nt++) {
                int bb = bBase + nt * (8 * LDP) + k0;
                uint32_t bh0 = __float_as_uint(S[OFF_BHI + bb]);
                uint32_t bh1 = __float_as_uint(S[OFF_BHI + bb + 4]);
                uint32_t bl0 = __float_as_uint(S[OFF_BLO + bb]);
                uint32_t bl1 = __float_as_uint(S[OFF_BLO + bb + 4]);
                #pragma unroll
                for (int mt = 0; mt < 2; mt++) {
                    MMA_TF32(d[mt][nt], ah[mt], bh0, bh1);
                    MMA_TF32(d[mt][nt], ah[mt], bl0, bl1);
                    MMA_TF32(d[mt][nt], al[mt], bh0, bh1);
                }
            }
        }
        __syncthreads();
        if (kt + 1 < NKT) {
            sts((kt + 1) & 1);
            __syncthreads();
        }
    }

    // ---- epilogue: direct fragment stores (float2), fused residual --------
    #pragma unroll
    for (int mt = 0; mt < 2; mt++) {
        int row = bm * 128 + wm * 32 + mt * 16 + g;
        #pragma unroll
        for (int nt = 0; nt < 8; nt++) {
            int col = bn * 128 + wn * 64 + nt * 8 + t * 2;
            if (col < N) {
                size_t i0 = (size_t)row * N + col;
                size_t i1 = (size_t)(row + 8) * N + col;
                float2 v0 = make_float2(d[mt][nt][0], d[mt][nt][1]);
                float2 v1 = make_float2(d[mt][nt][2], d[mt][nt][3]);
                if (SECOND) {
                    float2 r0v = *(const float2*)(resid + i0);
                    float2 r1v = *(const float2*)(resid + i1);
                    v0.x += r0v.x; v0.y += r0v.y;
                    v1.x += r1v.x; v1.y += r1v.y;
                }
                *(float2*)(Cptr + i0) = v0;
                *(float2*)(Cptr + i1) = v1;
            }
        }
    }
}

// ---------------- block reduction helper -----------------------------------
__device__ __forceinline__ float block_sum256(float v, float* sh) {
    #pragma unroll
    for (int o = 16; o; o >>= 1) v += __shfl_xor_sync(0xffffffffu, v, o);
    int lane = threadIdx.x & 31, wid = threadIdx.x >> 5;
    __syncthreads();
    if (lane == 0) sh[wid] = v;
    __syncthreads();
    float tt = 0.f;
    #pragma unroll
    for (int j = 0; j < 8; j++) tt += sh[j];
    return tt;
}

// ---------------- profiling-slot no-op -------------------------------------
__global__ void noop_kernel() {}

// ---------------- 1) LayerNorm ---------------------------------------------
__global__ void __launch_bounds__(256) ln_kernel(const float* __restrict__ x,
                                                 const float* __restrict__ w,
                                                 const float* __restrict__ bparm)
{
    __shared__ float sh[8];
    int row = blockIdx.x, tid = threadIdx.x;
    const float4* xr = (const float4*)(x + (size_t)row * DMODEL);
    float4 v = xr[tid];
    float s  = v.x + v.y + v.z + v.w;
    float mu = block_sum256(s, sh) * (1.f / DMODEL);
    float d0 = v.x - mu, d1 = v.y - mu, d2 = v.z - mu, d3 = v.w - mu;
    float vs = d0*d0 + d1*d1 + d2*d2 + d3*d3;
    float var = block_sum256(vs, sh) * (1.f / DMODEL);
    float inv = rsqrtf(var + 1e-5f);
    float4 wv = ((const float4*)w)[tid];
    float4 bv = ((const float4*)bparm)[tid];
    float4 o;
    o.x = d0 * inv * wv.x + bv.x;
    o.y = d1 * inv * wv.y + bv.y;
    o.z = d2 * inv * wv.z + bv.z;
    o.w = d3 * inv * wv.w + bv.w;
    ((float4*)(g_u + (size_t)row * DMODEL))[tid] = o;
}

// ---------------- 3) causal depthwise conv(4) + SiLU -----------------------
__global__ void __launch_bounds__(256) conv_silu_kernel(const float* __restrict__ conv_w,
                                                        const float* __restrict__ conv_b)
{
    int i = blockIdx.y;
    int c = blockIdx.x * 256 + threadIdx.x;
    if (c >= CONVDIM) return;
    int b = i >> 12;
    int l = i & 4095;
    float w0 = conv_w[c*4+0], w1 = conv_w[c*4+1];
    float w2 = conv_w[c*4+2], w3 = conv_w[c*4+3];
    const float* col = g_zx + (size_t)(b << 12) * DINPROJ + DINNER + c;
    float s = conv_b[c];
    if (l >= 3) s += col[(size_t)(l-3) * DINPROJ] * w0;
    if (l >= 2) s += col[(size_t)(l-2) * DINPROJ] * w1;
    if (l >= 1) s += col[(size_t)(l-1) * DINPROJ] * w2;
    s += col[(size_t)l * DINPROJ] * w3;
    s = s / (1.f + expf(-s));
    g_xbca[(size_t)i * CONVDIM + c] = s;
}

// ---------------- 3b) softplus(dt + dt_bias) -------------------------------
__global__ void __launch_bounds__(256) dt_kernel(const float* __restrict__ dt_bias)
{
    int idx = blockIdx.x * 256 + threadIdx.x;
    int i = idx >> 5, hh = idx & 31;
    float v = g_zx[(size_t)i * DINPROJ + (DINNER + CONVDIM) + hh] + dt_bias[hh];
    g_dt[idx] = (v > 20.f) ? v : log1pf(expf(v));
}

// ---------------- 4) sequential selective-state scan -----------------------
// grid = BATCH*NHEADS*2 = 128 blocks (p split in halves of 32), 256 threads.
// Thread (tid): p = half*32 + tid/8, owns n = (tid&7)*8 .. +8 states.
// Depth-8 cp.async ring stages {x, B, C, dt} per step (672B/slot).
#define RING_F 168                 // floats per slot (x32, B64, C64, dt1, pad)
__global__ void __launch_bounds__(256) scan_kernel(const float* __restrict__ A_log,
                                                   const float* __restrict__ Dp)
{
    __shared__ __align__(16) float ring[8][RING_F];

    int bx   = blockIdx.x;
    int b    = bx >> 6;
    int h    = (bx >> 1) & 31;
    int half = bx & 1;
    int tid  = threadIdx.x;
    int pl   = tid >> 3;
    int p    = half * 32 + pl;
    int nb   = (tid & 7) * 8;

    float Ah = -expf(A_log[h]);
    float Dh = Dp[h];

    float hreg[8];
    #pragma unroll
    for (int j = 0; j < 8; j++) hreg[j] = 0.f;

    const float* base = g_xbca + (size_t)b * SEQLEN * CONVDIM;
    const float* xsrc = base + h * 64 + half * 32;
    const float* bsrc = base + 2048;
    const float* csrc = base + 2112;
    const float* dsrc = g_dt + (size_t)b * SEQLEN * NHEADS + h;
    float*       yb   = g_y  + (size_t)b * SEQLEN * DINNER + h * HEADDIM + p;

    uint32_t rbase = smem_u32(&ring[0][0]);

    auto issue = [&](int t) {
        if (t < SEQLEN && tid < 41) {
            uint32_t dst = rbase + (uint32_t)(t & 7) * (RING_F * 4);
            size_t roff = (size_t)t * CONVDIM;
            if (tid < 8)       CP_ASYNC16(dst + tid * 16,              xsrc + roff + tid * 4);
            else if (tid < 24) CP_ASYNC16(dst + 128 + (tid - 8) * 16,  bsrc + roff + (tid - 8) * 4);
            else if (tid < 40) CP_ASYNC16(dst + 384 + (tid - 24) * 16, csrc + roff + (tid - 24) * 4);
            else               CP_ASYNC4 (dst + 640,                   dsrc + (size_t)t * NHEADS);
        }
        CP_COMMIT();
    };

    #pragma unroll
    for (int t = 0; t < 7; t++) issue(t);

    for (int t = 0; t < SEQLEN; t++) {
        CP_WAIT6();
        __syncthreads();
        issue(t + 7);

        const float* S = ring[t & 7];
        float dt_c = S[160];
        float xv_c = S[pl];
        float4 B0c = *(const float4*)(S + 32 + nb);
        float4 B1c = *(const float4*)(S + 32 + nb + 4);
        float4 C0c = *(const float4*)(S + 96 + nb);
        float4 C1c = *(const float4*)(S + 96 + nb + 4);

        float dA  = expf(dt_c * Ah);
        float dtx = dt_c * xv_c;

        float acc0, acc1;
        hreg[0] = hreg[0] * dA + dtx * B0c.x;  acc0  = hreg[0] * C0c.x;
        hreg[1] = hreg[1] * dA + dtx * B0c.y;  acc1  = hreg[1] * C0c.y;
        hreg[2] = hreg[2] * dA + dtx * B0c.z;  acc0 += hreg[2] * C0c.z;
        hreg[3] = hreg[3] * dA + dtx * B0c.w;  acc1 += hreg[3] * C0c.w;
        hreg[4] = hreg[4] * dA + dtx * B1c.x;  acc0 += hreg[4] * C1c.x;
        hreg[5] = hreg[5] * dA + dtx * B1c.y;  acc1 += hreg[5] * C1c.y;
        hreg[6] = hreg[6] * dA + dtx * B1c.z;  acc0 += hreg[6] * C1c.z;
        hreg[7] = hreg[7] * dA + dtx * B1c.w;  acc1 += hreg[7] * C1c.w;
        float acc = acc0 + acc1;

        acc += __shfl_xor_sync(0xffffffffu, acc, 1, 8);
        acc += __shfl_xor_sync(0xffffffffu, acc, 2, 8);
        acc += __shfl_xor_sync(0xffffffffu, acc, 4, 8);
        if ((tid & 7) == 0)
            yb[(size_t)t * DINNER] = acc + Dh * xv_c;
    }
}

// ---------------- 5) gate (y * silu(z)) + RMSNorm --------------------------
__global__ void __launch_bounds__(256) gate_rms_kernel(const float* __restrict__ norm_w)
{
    __shared__ float sh[8];
    int row = blockIdx.x, tid = threadIdx.x;
    const float4* y4 = (const float4*)(g_y  + (size_t)row * DINNER);
    const float4* z4 = (const float4*)(g_zx + (size_t)row * DINPROJ);
    float4 a0 = y4[tid], a1 = y4[tid + 256];
    float4 z0 = z4[tid], z1 = z4[tid + 256];
    float g[8];
    g[0] = a0.x * (z0.x / (1.f + expf(-z0.x)));
    g[1] = a0.y * (z0.y / (1.f + expf(-z0.y)));
    g[2] = a0.z * (z0.z / (1.f + expf(-z0.z)));
    g[3] = a0.w * (z0.w / (1.f + expf(-z0.w)));
    g[4] = a1.x * (z1.x / (1.f + expf(-z1.x)));
    g[5] = a1.y * (z1.y / (1.f + expf(-z1.y)));
    g[6] = a1.z * (z1.z / (1.f + expf(-z1.z)));
    g[7] = a1.w * (z1.w / (1.f + expf(-z1.w)));
    float ss = 0.f;
    #pragma unroll
    for (int j = 0; j < 8; j++) ss += g[j] * g[j];
    float tot = block_sum256(ss, sh);
    float inv = rsqrtf(tot * (1.f / DINNER) + 1e-5f);
    float4 w0 = ((const float4*)norm_w)[tid];
    float4 w1 = ((const float4*)norm_w)[tid + 256];
    float4 o0, o1;
    o0.x = g[0] * inv * w0.x; o0.y = g[1] * inv * w0.y;
    o0.z = g[2] * inv * w0.z; o0.w = g[3] * inv * w0.w;
    o1.x = g[4] * inv * w1.x; o1.y = g[5] * inv * w1.y;
    o1.z = g[6] * inv * w1.z; o1.w = g[7] * inv * w1.w;
    float4* yn4 = (float4*)(g_yn + (size_t)row * DINNER);
    yn4[tid] = o0;
    yn4[tid + 256] = o1;
}

// ---------------- launcher -------------------------------------------------
extern "C" void kernel_launch(void* const* d_in, const int* in_sizes, int n_in,
                              void* d_out, int out_size)
{
    const float* x       = (const float*)d_in[0];
    const float* ln_w    = (const float*)d_in[1];
    const float* ln_b    = (const float*)d_in[2];
    const float* W_in    = (const float*)d_in[3];
    const float* conv_w  = (const float*)d_in[4];
    const float* conv_b  = (const float*)d_in[5];
    const float* dt_bias = (const float*)d_in[6];
    const float* A_log   = (const float*)d_in[7];
    const float* Dp      = (const float*)d_in[8];
    const float* norm_w  = (const float*)d_in[9];
    const float* W_out   = (const float*)d_in[10];
    float* out = (float*)d_out;

    cudaFuncSetAttribute(gemm_tc<DINPROJ, DMODEL, false>,
                         cudaFuncAttributeMaxDynamicSharedMemorySize, SMEM_DYN);
    cudaFuncSetAttribute(gemm_tc<DMODEL, DINNER, true>,
                         cudaFuncAttributeMaxDynamicSharedMemorySize, SMEM_DYN);

    ln_kernel<<<BL, 256>>>(x, ln_w, ln_b);          // launch 1

    noop_kernel<<<1, 32>>>();                       // launch 2 (profiler align)
    noop_kernel<<<1, 32>>>();                       // launch 3 (profiler align)

    gemm_tc<DINPROJ, DMODEL, false>                 // launch 4 <- ncu window
        <<<dim3((DINPROJ + 127) / 128, BL / 128), 256, SMEM_DYN>>>(W_in, nullptr, nullptr);

    conv_silu_kernel<<<dim3((CONVDIM + 255) / 256, BL), 256>>>(conv_w, conv_b);
    dt_kernel<<<BL * NHEADS / 256, 256>>>(dt_bias);

    scan_kernel<<<BATCH * NHEADS * 2, 256>>>(A_log, Dp);

    gate_rms_kernel<<<BL, 256>>>(norm_w);

    gemm_tc<DMODEL, DINNER, true>
        <<<dim3(DMODEL / 128, BL / 128), 256, SMEM_DYN>>>(W_out, x, out);
}